// round 15
// baseline (speedup 1.0000x reference)
#include <cuda_runtime.h>
#include <cuda_bf16.h>
#include <math.h>
#include <stdint.h>

// Problem constants
#define Bb   2
#define Tt   2048
#define Dd   2048
#define Hh   16
#define HDd  128
#define LATd 512
#define RDd  64
#define CDd  64
#define Mrows (Bb*Tt)   // 4096

// ---------------------------------------------------------------------------
// Scratch (static device globals; no allocation allowed)
// ---------------------------------------------------------------------------
__device__ float g_q [Mrows * (Hh*HDd)];
__device__ float g_kv[Mrows * (2*LATd)];
__device__ float g_kr[Mrows * RDd];
__device__ float g_kc[Mrows * (Hh*CDd)];
__device__ float g_v [Mrows * (Hh*HDd)];
__device__ float g_ao[Mrows * (Hh*HDd)];
__device__ float g_xt[Mrows * Dd];            // x pre-converted to tf32 bits

// pre-converted weights, one pool (offsets in floats)
#define OFF_WQ  0
#define OFF_WKV (OFF_WQ  + 2048*2048)
#define OFF_WKR (OFF_WKV + 1024*2048)
#define OFF_WKU (OFF_WKR + 64*2048)
#define OFF_WVU (OFF_WKU + 1024*512)
#define OFF_WO  (OFF_WVU + 2048*512)
#define WT_TOTAL (OFF_WO + 2048*2048)
__device__ float g_wt[WT_TOTAL];

// ---------------------------------------------------------------------------
// tf32 helpers (fragment layouts HW-validated rounds 3-14)
// ---------------------------------------------------------------------------
__device__ __forceinline__ uint32_t f2tf32(float f) {
    uint32_t r;
    asm("cvt.rna.tf32.f32 %0, %1;" : "=r"(r) : "f"(f));
    return r;
}
__device__ __forceinline__ float truncf32(float f) {
    return __uint_as_float(f2tf32(f));
}

__device__ __forceinline__ void mma_tf32(
    float& c0, float& c1, float& c2, float& c3,
    uint32_t a0, uint32_t a1, uint32_t a2, uint32_t a3,
    uint32_t b0, uint32_t b1)
{
    asm volatile(
        "mma.sync.aligned.m16n8k8.row.col.f32.tf32.tf32.f32 "
        "{%0,%1,%2,%3}, {%4,%5,%6,%7}, {%8,%9}, {%0,%1,%2,%3};\n"
        : "+f"(c0), "+f"(c1), "+f"(c2), "+f"(c3)
        : "r"(a0), "r"(a1), "r"(a2), "r"(a3), "r"(b0), "r"(b1));
}

__device__ __forceinline__ void ldsm_x4(
    uint32_t& r0, uint32_t& r1, uint32_t& r2, uint32_t& r3, uint32_t addr)
{
    asm volatile("ldmatrix.sync.aligned.m8n8.x4.shared.b16 {%0,%1,%2,%3}, [%4];"
                 : "=r"(r0), "=r"(r1), "=r"(r2), "=r"(r3) : "r"(addr));
}

__device__ __forceinline__ void cp_async16(uint32_t dst_smem, const void* src, int src_bytes) {
    asm volatile("cp.async.cg.shared.global [%0], [%1], 16, %2;\n"
                 :: "r"(dst_smem), "l"(src), "r"(src_bytes));
}
#define CP_COMMIT() asm volatile("cp.async.commit_group;\n" ::: "memory")
#define CP_WAIT1()  asm volatile("cp.async.wait_group 1;\n" ::: "memory")
#define CP_WAIT0()  asm volatile("cp.async.wait_group 0;\n" ::: "memory")

// ---------------------------------------------------------------------------
// Prepass: convert x and all weights to tf32 bits (one launch).
// ---------------------------------------------------------------------------
#define CVT_BLOCKS (2048 + 1024 + 512 + 32 + 128 + 256 + 1024)   // 5024

__global__ void __launch_bounds__(256) cvt_all(
    const float* __restrict__ x,
    const float* __restrict__ Wq,  const float* __restrict__ Wkv,
    const float* __restrict__ Wkr, const float* __restrict__ Wku,
    const float* __restrict__ Wvu, const float* __restrict__ Wo,
    float* __restrict__ xt, float* __restrict__ wt)
{
    int b = blockIdx.x;
    const float* src; float* dst; int base;
    if      (b < 2048) { src = x;   dst = xt;           base = b; }
    else if (b < 3072) { src = Wq;  dst = wt + OFF_WQ;  base = b - 2048; }
    else if (b < 3584) { src = Wkv; dst = wt + OFF_WKV; base = b - 3072; }
    else if (b < 3616) { src = Wkr; dst = wt + OFF_WKR; base = b - 3584; }
    else if (b < 3744) { src = Wku; dst = wt + OFF_WKU; base = b - 3616; }
    else if (b < 4000) { src = Wvu; dst = wt + OFF_WVU; base = b - 3744; }
    else               { src = Wo;  dst = wt + OFF_WO;  base = b - 4000; }

    #pragma unroll
    for (int it = 0; it < 4; it++) {
        int i = base * 1024 + it * 256 + threadIdx.x;
        float4 v = ((const float4*)src)[i];
        uint4 u;
        u.x = f2tf32(v.x); u.y = f2tf32(v.y);
        u.z = f2tf32(v.z); u.w = f2tf32(v.w);
        ((uint4*)dst)[i] = u;
    }
}

// ---------------------------------------------------------------------------
// TF32 GEMM core: 128x256x32 tiles, 512 threads (16 warps), warp tile 32x64.
// ldmatrix fragment loads, 3-stage cp.async pipeline. 1 CTA/SM (166 KB smem),
// 16 warps/SM (same as before), -27% L2 traffic vs 128x128.
// ---------------------------------------------------------------------------
#define GBM 128
#define GBN 256
#define BK 32
#define GST 36
#define G_ASZ (GBM*GST)           // 4608
#define G_BSZ (GBN*GST)           // 9216
#define GSTG 3
#define GEMM_SMEM_BYTES ((GSTG*G_ASZ + GSTG*G_BSZ) * 4)   // 165888 B
#define GTH 512

__device__ __forceinline__ void gemm_core(
    const float* __restrict__ A, int lda,
    const float* __restrict__ W,
    const float* __restrict__ bias,
    float* __restrict__ C, int ldc,
    int Nloc, int K, int bm, int bnl, bool trunc,
    float* smemf)
{
    const uint32_t smem_u32 = (uint32_t)__cvta_generic_to_shared(smemf);

    const int tid  = threadIdx.x;
    const int warp = tid >> 5;          // 0..15
    const int lane = tid & 31;
    const int g    = lane >> 2;
    const int tg   = lane & 3;
    const int wm   = warp & 3;          // 4 warps along M (32 rows each)
    const int wn   = warp >> 2;         // 4 warps along N (64 cols each)
    const int wr0  = wm * 32;
    const int wn0  = wn * 64;

    // ldmatrix lane address bases (byte offsets within a stage)
    const uint32_t aBase = smem_u32 + (uint32_t)(
        ((wr0 + (lane & 7) + ((lane >> 3) & 1) * 8) * GST + (lane >> 4) * 4) * 4);
    const uint32_t bBase = smem_u32 + (uint32_t)(
        (GSTG * G_ASZ +
         (wn0 + (lane >> 4) * 8 + (lane & 7)) * GST + ((lane >> 3) & 1) * 4) * 4);

    float acc[2][8][4];
    #pragma unroll
    for (int mi = 0; mi < 2; mi++)
        #pragma unroll
        for (int ni = 0; ni < 8; ni++)
            #pragma unroll
            for (int r = 0; r < 4; r++) acc[mi][ni][r] = 0.f;

    const int ntiles = K / BK;
    const int lk4 = (tid & 7) * 4;

    auto prefetch = [&](int k0, int s) {
        // A: 128x32 = 1024 chunks, 2 per thread
        #pragma unroll
        for (int it = 0; it < 2; it++) {
            int id  = tid + it * GTH;
            int row = id >> 3;
            uint32_t adst = smem_u32 + (uint32_t)((s*G_ASZ + row*GST + lk4) * 4);
            cp_async16(adst, A + (size_t)(bm + row) * lda + k0 + lk4, 16);
        }
        // B: 256x32 = 2048 chunks, 4 per thread
        #pragma unroll
        for (int it = 0; it < 4; it++) {
            int id  = tid + it * GTH;
            int row = id >> 3;
            int nrow = bnl + row;
            uint32_t bdst = smem_u32 + (uint32_t)(((GSTG*G_ASZ) + s*G_BSZ + row*GST + lk4) * 4);
            cp_async16(bdst, W + (size_t)(nrow < Nloc ? nrow : 0) * K + k0 + lk4,
                       nrow < Nloc ? 16 : 0);
        }
    };

    prefetch(0, 0);      CP_COMMIT();
    prefetch(BK, 1);     CP_COMMIT();

    int st = 0, ps = 2;
    for (int t = 0; t < ntiles; t++) {
        CP_WAIT1();
        __syncthreads();
        if (t + 2 < ntiles) prefetch((t + 2) * BK, ps);
        CP_COMMIT();

        const uint32_t aOff = (uint32_t)(st * G_ASZ * 4);
        const uint32_t bOff = (uint32_t)(st * G_BSZ * 4);

        #pragma unroll
        for (int kk = 0; kk < BK; kk += 8) {
            uint32_t af[2][4], bf[8][2];
            #pragma unroll
            for (int mi = 0; mi < 2; mi++)
                ldsm_x4(af[mi][0], af[mi][1], af[mi][2], af[mi][3],
                        aBase + aOff + (uint32_t)((mi*16*GST + kk) * 4));
            #pragma unroll
            for (int p = 0; p < 4; p++)
                ldsm_x4(bf[2*p][0], bf[2*p][1], bf[2*p+1][0], bf[2*p+1][1],
                        bBase + bOff + (uint32_t)((p*16*GST + kk) * 4));
            #pragma unroll
            for (int mi = 0; mi < 2; mi++)
                #pragma unroll
                for (int ni = 0; ni < 8; ni++)
                    mma_tf32(acc[mi][ni][0], acc[mi][ni][1],
                             acc[mi][ni][2], acc[mi][ni][3],
                             af[mi][0], af[mi][1], af[mi][2], af[mi][3],
                             bf[ni][0], bf[ni][1]);
        }
        st = (st == 2) ? 0 : st + 1;
        ps = (ps == 2) ? 0 : ps + 1;
    }

    #pragma unroll
    for (int mi = 0; mi < 2; mi++) {
        int row0 = bm + wr0 + mi * 16 + g;
        #pragma unroll
        for (int ni = 0; ni < 8; ni++) {
            int col = bnl + wn0 + ni * 8 + 2 * tg;
            if (col < Nloc) {
                float b0 = bias[col];
                float b1 = bias[col + 1];
                float r0 = acc[mi][ni][0] + b0;
                float r1 = acc[mi][ni][1] + b1;
                float r2 = acc[mi][ni][2] + b0;
                float r3 = acc[mi][ni][3] + b1;
                if (trunc) {
                    r0 = truncf32(r0); r1 = truncf32(r1);
                    r2 = truncf32(r2); r3 = truncf32(r3);
                }
                float* p0 = C + (size_t)row0 * ldc + col;
                float* p1 = C + (size_t)(row0 + 8) * ldc + col;
                p0[0] = r0; p0[1] = r1;
                p1[0] = r2; p1[1] = r3;
            }
        }
    }
}

// ---- fused q | kv | kr projection: N sections 2048(8 blk) | 1024(4) | 64(1) ----
__global__ void __launch_bounds__(GTH, 1) gemm_qkvkr(
    const float* __restrict__ xt,
    const float* __restrict__ wt,
    const float* __restrict__ bq,
    const float* __restrict__ bkv,
    const float* __restrict__ bkr,
    float* __restrict__ qb, float* __restrict__ kvb, float* __restrict__ krb)
{
    extern __shared__ float smemf[];
    int bn = blockIdx.x * GBN;
    const float *W, *bias; float* C; int ldc, Nloc, bnl; bool trunc;
    if (bn < 2048)      { W = wt + OFF_WQ;  bias = bq;  C = qb;  ldc = 2048; Nloc = 2048; bnl = bn;        trunc = false; }
    else if (bn < 3072) { W = wt + OFF_WKV; bias = bkv; C = kvb; ldc = 1024; Nloc = 1024; bnl = bn - 2048; trunc = true;  }
    else                { W = wt + OFF_WKR; bias = bkr; C = krb; ldc = 64;   Nloc = 64;   bnl = bn - 3072; trunc = false; }
    gemm_core(xt, Dd, W, bias, C, ldc, Nloc, Dd, blockIdx.y * GBM, bnl, trunc, smemf);
}

// ---------------------------------------------------------------------------
// RoPE pair helper
// ---------------------------------------------------------------------------
__device__ __forceinline__ void rope_pair_t(float* p, int i, int t, bool trunc)
{
    float inv_freq = powf(10000.f, -(float)i / 32.f);
    float ang = (float)t * inv_freq;
    float s, c;
    sincosf(ang, &s, &c);
    float x1 = p[i];
    float x2 = p[i + 32];
    float y1 = x1 * c - x2 * s;
    float y2 = x2 * c + x1 * s;
    p[i]      = trunc ? truncf32(y1) : y1;
    p[i + 32] = trunc ? truncf32(y2) : y2;
}

#define KUVU_GEMM_BX 12     // ku 4 blocks + vu 8 blocks
#define KUVU_ROPE_BX 128

__global__ void __launch_bounds__(GTH, 1) gemm_kuvu_rope(
    const float* __restrict__ kvb,
    const float* __restrict__ wt,
    const float* __restrict__ bku,
    const float* __restrict__ bvu,
    float* __restrict__ kcb, float* __restrict__ vb,
    float* __restrict__ qb, float* __restrict__ krb)
{
    extern __shared__ float smemf[];
    if (blockIdx.x >= KUVU_GEMM_BX) {
        int row = blockIdx.y * KUVU_ROPE_BX + (blockIdx.x - KUVU_GEMM_BX);
        int t   = row & (Tt - 1);
        for (int item = threadIdx.x; item < 544; item += GTH) {
            if (item < 32)
                rope_pair_t(krb + (size_t)row * RDd, item, t, true);
            else {
                int h = (item - 32) >> 5;
                int i = (item - 32) & 31;
                rope_pair_t(qb + (size_t)row * (Hh*HDd) + h*HDd + CDd, i, t, false);
            }
        }
        return;
    }
    int bn = blockIdx.x * GBN;
    const float* A; const float *W, *bias; float* C; int ldc, Nloc, bnl;
    if (bn < 1024) { A = kvb;        W = wt + OFF_WKU; bias = bku; C = kcb; ldc = 1024; Nloc = 1024; bnl = bn; }
    else           { A = kvb + LATd; W = wt + OFF_WVU; bias = bvu; C = vb;  ldc = 2048; Nloc = 2048; bnl = bn - 1024; }
    gemm_core(A, 2*LATd, W, bias, C, ldc, Nloc, LATd, blockIdx.y * GBM, bnl, true, smemf);
}

__global__ void __launch_bounds__(GTH, 1) gemm_out(
    const float* __restrict__ ob,
    const float* __restrict__ wt,
    const float* __restrict__ bo,
    float* __restrict__ out)
{
    extern __shared__ float smemf[];
    gemm_core(ob, Hh*HDd, wt + OFF_WO, bo, out, Dd, Dd, Dd,
              blockIdx.y * GBM, blockIdx.x * GBN, false, smemf);
}

// ---------------------------------------------------------------------------
// Tensor-core flash attention (R14 structure): 64-row q blocks, 128 threads,
// single-buffered K/V, 2 CTAs/SM, ldmatrix K/P frags, V via LDS.
// NEW: log2e folded into scale -> exp2f (one less FMUL per exp).
// ---------------------------------------------------------------------------
#define A3_SK 132
#define A3_SV 136
#define A3_SP 68
#define A3_SMEM_BYTES ((64*A3_SK + 64*A3_SV + 64*A3_SP) * 4)   // 86016 B

__global__ void __launch_bounds__(128, 2) attn_mma_kernel(
    const float* __restrict__ q,
    const float* __restrict__ kc,
    const float* __restrict__ kr,
    const float* __restrict__ v,
    float* __restrict__ o)
{
    extern __shared__ float smf[];
    float*    Ksf = smf;
    float*    Vsf = smf + 64*A3_SK;
    uint32_t* Ps  = (uint32_t*)(smf + 64*A3_SK + 64*A3_SV);
    const uint32_t smem_u32 = (uint32_t)__cvta_generic_to_shared(smf);

    const int qt   = (Tt/64 - 1) - blockIdx.x;
    const int h    = blockIdx.y;
    const int b    = blockIdx.z;
    const int tid  = threadIdx.x;
    const int warp = tid >> 5;
    const int lane = tid & 31;
    const int g    = lane >> 2;
    const int tg   = lane & 3;
    const int m0   = warp * 16;
    const int qbase = qt * 64;
    const size_t rowbase = (size_t)b * Tt;
    const float scale2 = 0.08838834764831845f * 1.4426950408889634f;  // /sqrt(128)*log2e

    const uint32_t kBase = smem_u32 + (uint32_t)(
        (((lane >> 4) * 8 + (lane & 7)) * A3_SK + ((lane >> 3) & 1) * 4) * 4);
    const uint32_t pBase = smem_u32 + (uint32_t)(
        ((64*A3_SK + 64*A3_SV) +
         (m0 + (lane & 7) + ((lane >> 3) & 1) * 8) * A3_SP + (lane >> 4) * 4) * 4);

    uint32_t aq[16][4];
    {
        const float* qA = q + (rowbase + qbase + m0 + g) * (Hh*HDd) + h*HDd;
        const float* qB = qA + 8 * (Hh*HDd);
        #pragma unroll
        for (int ks = 0; ks < 16; ks++) {
            int k0 = ks * 8;
            aq[ks][0] = f2tf32(qA[k0 + tg]);
            aq[ks][1] = f2tf32(qB[k0 + tg]);
            aq[ks][2] = f2tf32(qA[k0 + tg + 4]);
            aq[ks][3] = f2tf32(qB[k0 + tg + 4]);
        }
    }

    float oacc[16][4];
    #pragma unroll
    for (int na = 0; na < 16; na++)
        #pragma unroll
        for (int r = 0; r < 4; r++) oacc[na][r] = 0.f;

    float mA = -INFINITY, mB = -INFINITY;
    float lA = 0.f, lB = 0.f;

    const int rAg = qbase + m0 + g;
    const int rBg = rAg + 8;

    for (int kb = 0; kb <= qt; kb++) {
        const int kbase = kb * 64;

        #pragma unroll
        for (int it = 0; it < 16; it++) {
            int i  = tid + it * 128;
            int rr = i >> 5;
            int c4 = i & 31;
            size_t trow = rowbase + kbase + rr;
            const float* ksrc = (c4 < 16)
                ? (kc + trow * (Hh*CDd) + h*CDd + c4*4)
                : (kr + trow * RDd + (c4-16)*4);
            uint32_t kdst = smem_u32 + (uint32_t)((rr*A3_SK + c4*4) * 4);
            cp_async16(kdst, ksrc, 16);
            const float* vsrc = v + trow * (Hh*HDd) + h*HDd + c4*4;
            uint32_t vdst = smem_u32 + (uint32_t)((64*A3_SK + rr*A3_SV + c4*4) * 4);
            cp_async16(vdst, vsrc, 16);
        }
        CP_COMMIT();
        CP_WAIT0();
        __syncthreads();

        const uint32_t* Vst = (const uint32_t*)Vsf;

        float sacc[8][4];
        #pragma unroll
        for (int na = 0; na < 8; na++)
            #pragma unroll
            for (int r = 0; r < 4; r++) sacc[na][r] = 0.f;

        #pragma unroll
        for (int ks = 0; ks < 16; ks++) {
            uint32_t kb_[8][2];
            #pragma unroll
            for (int p = 0; p < 4; p++)
                ldsm_x4(kb_[2*p][0], kb_[2*p][1], kb_[2*p+1][0], kb_[2*p+1][1],
                        kBase + (uint32_t)((p*16*A3_SK + ks*8) * 4));
            #pragma unroll
            for (int na = 0; na < 8; na++)
                mma_tf32(sacc[na][0], sacc[na][1], sacc[na][2], sacc[na][3],
                         aq[ks][0], aq[ks][1], aq[ks][2], aq[ks][3],
                         kb_[na][0], kb_[na][1]);
        }

        const bool needmask = (kbase + 63 > rAg);
        float mxA = -INFINITY, mxB = -INFINITY;
        #pragma unroll
        for (int na = 0; na < 8; na++) {
            float s0 = sacc[na][0] * scale2;
            float s1 = sacc[na][1] * scale2;
            float s2 = sacc[na][2] * scale2;
            float s3 = sacc[na][3] * scale2;
            if (needmask) {
                int cg = kbase + na*8 + 2*tg;
                if (cg     > rAg) s0 = -INFINITY;
                if (cg + 1 > rAg) s1 = -INFINITY;
                if (cg     > rBg) s2 = -INFINITY;
                if (cg + 1 > rBg) s3 = -INFINITY;
            }
            sacc[na][0] = s0; sacc[na][1] = s1;
            sacc[na][2] = s2; sacc[na][3] = s3;
            mxA = fmaxf(mxA, fmaxf(s0, s1));
            mxB = fmaxf(mxB, fmaxf(s2, s3));
        }
        mxA = fmaxf(mxA, __shfl_xor_sync(0xffffffff, mxA, 1));
        mxA = fmaxf(mxA, __shfl_xor_sync(0xffffffff, mxA, 2));
        mxB = fmaxf(mxB, __shfl_xor_sync(0xffffffff, mxB, 1));
        mxB = fmaxf(mxB, __shfl_xor_sync(0xffffffff, mxB, 2));

        float mnA = fmaxf(mA, mxA);
        float mnB = fmaxf(mB, mxB);
        float cfA = exp2f(mA - mnA);
        float cfB = exp2f(mB - mnB);
        mA = mnA; mB = mnB;

        float sumA = 0.f, sumB = 0.f;
        uint32_t* prowA = Ps + (m0 + g) * A3_SP;
        uint32_t* prowB = prowA + 8 * A3_SP;
        #pragma unroll
        for (int na = 0; na < 8; na++) {
            int c = na*8 + 2*tg;
            float p0 = exp2f(sacc[na][0] - mA);
            float p1 = exp2f(sacc[na][1] - mA);
            float p2 = exp2f(sacc[na][2] - mB);
            float p3 = exp2f(sacc[na][3] - mB);
            sumA += p0 + p1;
            sumB += p2 + p3;
            prowA[c]     = f2tf32(p0);
            prowA[c + 1] = f2tf32(p1);
            prowB[c]     = f2tf32(p2);
            prowB[c + 1] = f2tf32(p3);
        }
        lA = lA * cfA + sumA;
        lB = lB * cfB + sumB;

        #pragma unroll
        for (int na = 0; na < 16; na++) {
            oacc[na][0] *= cfA; oacc[na][1] *= cfA;
            oacc[na][2] *= cfB; oacc[na][3] *= cfB;
        }

        __syncwarp();

        #pragma unroll
        for (int ks = 0; ks < 8; ks++) {
            uint32_t pa0, pa1, pa2, pa3;
            ldsm_x4(pa0, pa1, pa2, pa3, pBase + (uint32_t)((ks*8) * 4));
            #pragma unroll
            for (int na = 0; na < 16; na++) {
                uint32_t b0 = Vst[(ks*8 + tg)     * A3_SV + na*8 + g];
                uint32_t b1 = Vst[(ks*8 + tg + 4) * A3_SV + na*8 + g];
                mma_tf32(oacc[na][0], oacc[na][1], oacc[na][2], oacc[na][3],
                         pa0, pa1, pa2, pa3, b0, b1);
            }
        }
        __syncthreads();
    }

    lA += __shfl_xor_sync(0xffffffff, lA, 1);
    lA += __shfl_xor_sync(0xffffffff, lA, 2);
    lB += __shfl_xor_sync(0xffffffff, lB, 1);
    lB += __shfl_xor_sync(0xffffffff, lB, 2);
    float invA = 1.f / lA;
    float invB = 1.f / lB;

    float* oA = o + (rowbase + qbase + m0 + g) * (Hh*HDd) + h*HDd;
    float* oB = oA + 8 * (Hh*HDd);
    #pragma unroll
    for (int na = 0; na < 16; na++) {
        int c = na*8 + 2*tg;
        *(float2*)(oA + c) = make_float2(truncf32(oacc[na][0]*invA),
                                         truncf32(oacc[na][1]*invA));
        *(float2*)(oB + c) = make_float2(truncf32(oacc[na][2]*invB),
                                         truncf32(oacc[na][3]*invB));
    }
}

// ---------------------------------------------------------------------------
// Launch: 5 launches; attention is launch 4 (ncu slot).
// ---------------------------------------------------------------------------
extern "C" void kernel_launch(void* const* d_in, const int* in_sizes, int n_in,
                              void* d_out, int out_size)
{
    const float* x   = (const float*)d_in[0];
    const float* Wq  = (const float*)d_in[1];
    const float* bq  = (const float*)d_in[2];
    const float* Wkv = (const float*)d_in[3];
    const float* bkv = (const float*)d_in[4];
    const float* Wkr = (const float*)d_in[5];
    const float* bkr = (const float*)d_in[6];
    const float* Wku = (const float*)d_in[7];
    const float* bku = (const float*)d_in[8];
    const float* Wvu = (const float*)d_in[9];
    const float* bvu = (const float*)d_in[10];
    const float* Wo  = (const float*)d_in[11];
    const float* bo  = (const float*)d_in[12];
    float* out = (float*)d_out;

    float *qb, *kvb, *krb, *kcb, *vb, *ob, *xt, *wt;
    cudaGetSymbolAddress((void**)&qb,  g_q);
    cudaGetSymbolAddress((void**)&kvb, g_kv);
    cudaGetSymbolAddress((void**)&krb, g_kr);
    cudaGetSymbolAddress((void**)&kcb, g_kc);
    cudaGetSymbolAddress((void**)&vb,  g_v);
    cudaGetSymbolAddress((void**)&ob,  g_ao);
    cudaGetSymbolAddress((void**)&xt,  g_xt);
    cudaGetSymbolAddress((void**)&wt,  g_wt);

    cudaFuncSetAttribute(gemm_qkvkr,
                         cudaFuncAttributeMaxDynamicSharedMemorySize, GEMM_SMEM_BYTES);
    cudaFuncSetAttribute(gemm_kuvu_rope,
                         cudaFuncAttributeMaxDynamicSharedMemorySize, GEMM_SMEM_BYTES);
    cudaFuncSetAttribute(gemm_out,
                         cudaFuncAttributeMaxDynamicSharedMemorySize, GEMM_SMEM_BYTES);
    cudaFuncSetAttribute(attn_mma_kernel,
                         cudaFuncAttributeMaxDynamicSharedMemorySize, A3_SMEM_BYTES);

    // 1: convert x + all weights to tf32 bits
    cvt_all<<<CVT_BLOCKS, dim3(256)>>>(x, Wq, Wkv, Wkr, Wku, Wvu, Wo, xt, wt);

    // 2: fused q|kv|kr projection (N = 2048+1024+64 -> 13 col blocks of 256)
    gemm_qkvkr<<<dim3(13, 32), dim3(GTH), GEMM_SMEM_BYTES>>>(
        xt, wt, bq, bkv, bkr, qb, kvb, krb);

    // 3: fused ku|vu up-projection + rope (extra CTAs)
    gemm_kuvu_rope<<<dim3(KUVU_GEMM_BX + KUVU_ROPE_BX, 32), dim3(GTH), GEMM_SMEM_BYTES>>>(
        kvb, wt, bku, bvu, kcb, vb, qb, krb);

    // 4: attention (ncu target slot)
    attn_mma_kernel<<<dim3(Tt/64, Hh, Bb), dim3(128), A3_SMEM_BYTES>>>(qb, kcb, krb, vb, ob);

    // 5: output projection (N = 2048 -> 8 col blocks)
    gemm_out<<<dim3(8, 32), dim3(GTH), GEMM_SMEM_BYTES>>>(ob, wt, bo, out);
}

// round 17
// speedup vs baseline: 1.0547x; 1.0547x over previous
#include <cuda_runtime.h>
#include <cuda_bf16.h>
#include <math.h>
#include <stdint.h>

// Problem constants
#define Bb   2
#define Tt   2048
#define Dd   2048
#define Hh   16
#define HDd  128
#define LATd 512
#define RDd  64
#define CDd  64
#define Mrows (Bb*Tt)   // 4096

// ---------------------------------------------------------------------------
// Scratch (static device globals; no allocation allowed)
// ---------------------------------------------------------------------------
__device__ float g_q [Mrows * (Hh*HDd)];
__device__ float g_kv[Mrows * (2*LATd)];
__device__ float g_kr[Mrows * RDd];
__device__ float g_kc[Mrows * (Hh*CDd)];
__device__ float g_v [Mrows * (Hh*HDd)];
__device__ float g_ao[Mrows * (Hh*HDd)];
__device__ float g_xt[Mrows * Dd];            // x pre-converted to tf32 bits

// pre-converted weights, one pool (offsets in floats)
#define OFF_WQ  0
#define OFF_WKV (OFF_WQ  + 2048*2048)
#define OFF_WKR (OFF_WKV + 1024*2048)
#define OFF_WKU (OFF_WKR + 64*2048)
#define OFF_WVU (OFF_WKU + 1024*512)
#define OFF_WO  (OFF_WVU + 2048*512)
#define WT_TOTAL (OFF_WO + 2048*2048)
__device__ float g_wt[WT_TOTAL];

// ---------------------------------------------------------------------------
// tf32 helpers (fragment layouts HW-validated rounds 3-15)
// ---------------------------------------------------------------------------
__device__ __forceinline__ uint32_t f2tf32(float f) {
    uint32_t r;
    asm("cvt.rna.tf32.f32 %0, %1;" : "=r"(r) : "f"(f));
    return r;
}
__device__ __forceinline__ float truncf32(float f) {
    return __uint_as_float(f2tf32(f));
}

__device__ __forceinline__ void mma_tf32(
    float& c0, float& c1, float& c2, float& c3,
    uint32_t a0, uint32_t a1, uint32_t a2, uint32_t a3,
    uint32_t b0, uint32_t b1)
{
    asm volatile(
        "mma.sync.aligned.m16n8k8.row.col.f32.tf32.tf32.f32 "
        "{%0,%1,%2,%3}, {%4,%5,%6,%7}, {%8,%9}, {%0,%1,%2,%3};\n"
        : "+f"(c0), "+f"(c1), "+f"(c2), "+f"(c3)
        : "r"(a0), "r"(a1), "r"(a2), "r"(a3), "r"(b0), "r"(b1));
}

__device__ __forceinline__ void ldsm_x4(
    uint32_t& r0, uint32_t& r1, uint32_t& r2, uint32_t& r3, uint32_t addr)
{
    asm volatile("ldmatrix.sync.aligned.m8n8.x4.shared.b16 {%0,%1,%2,%3}, [%4];"
                 : "=r"(r0), "=r"(r1), "=r"(r2), "=r"(r3) : "r"(addr));
}

__device__ __forceinline__ void cp_async16(uint32_t dst_smem, const void* src, int src_bytes) {
    asm volatile("cp.async.cg.shared.global [%0], [%1], 16, %2;\n"
                 :: "r"(dst_smem), "l"(src), "r"(src_bytes));
}
#define CP_COMMIT() asm volatile("cp.async.commit_group;\n" ::: "memory")
#define CP_WAIT1()  asm volatile("cp.async.wait_group 1;\n" ::: "memory")
#define CP_WAIT0()  asm volatile("cp.async.wait_group 0;\n" ::: "memory")

// ---------------------------------------------------------------------------
// Prepass: convert x and all weights to tf32 bits (one launch).
// ---------------------------------------------------------------------------
#define CVT_BLOCKS (2048 + 1024 + 512 + 32 + 128 + 256 + 1024)   // 5024

__global__ void __launch_bounds__(256) cvt_all(
    const float* __restrict__ x,
    const float* __restrict__ Wq,  const float* __restrict__ Wkv,
    const float* __restrict__ Wkr, const float* __restrict__ Wku,
    const float* __restrict__ Wvu, const float* __restrict__ Wo,
    float* __restrict__ xt, float* __restrict__ wt)
{
    int b = blockIdx.x;
    const float* src; float* dst; int base;
    if      (b < 2048) { src = x;   dst = xt;           base = b; }
    else if (b < 3072) { src = Wq;  dst = wt + OFF_WQ;  base = b - 2048; }
    else if (b < 3584) { src = Wkv; dst = wt + OFF_WKV; base = b - 3072; }
    else if (b < 3616) { src = Wkr; dst = wt + OFF_WKR; base = b - 3584; }
    else if (b < 3744) { src = Wku; dst = wt + OFF_WKU; base = b - 3616; }
    else if (b < 4000) { src = Wvu; dst = wt + OFF_WVU; base = b - 3744; }
    else               { src = Wo;  dst = wt + OFF_WO;  base = b - 4000; }

    #pragma unroll
    for (int it = 0; it < 4; it++) {
        int i = base * 1024 + it * 256 + threadIdx.x;
        float4 v = ((const float4*)src)[i];
        uint4 u;
        u.x = f2tf32(v.x); u.y = f2tf32(v.y);
        u.z = f2tf32(v.z); u.w = f2tf32(v.w);
        ((uint4*)dst)[i] = u;
    }
}

// ---------------------------------------------------------------------------
// TF32 GEMM core (exact R14 config): 128x128x32 tiles, 256 threads,
// warp tile 64x32, ldmatrix fragment loads, 3-stage cp.async pipeline,
// __launch_bounds__(256,2) -> 2 CTAs/SM.
// ---------------------------------------------------------------------------
#define BM 128
#define BN 128
#define BK 32
#define GST 36
#define G_ASZ (BM*GST)
#define GSTG 3
#define GEMM_SMEM_BYTES (GSTG * 2 * G_ASZ * 4)   // 110592 B

__device__ __forceinline__ void gemm_core(
    const float* __restrict__ A, int lda,
    const float* __restrict__ W,
    const float* __restrict__ bias,
    float* __restrict__ C, int ldc,
    int Nloc, int K, int bm, int bnl, bool trunc,
    float* smemf)
{
    const uint32_t smem_u32 = (uint32_t)__cvta_generic_to_shared(smemf);

    const int tid  = threadIdx.x;
    const int warp = tid >> 5;
    const int lane = tid & 31;
    const int g    = lane >> 2;
    const int tg   = lane & 3;
    const int wm   = warp & 1;
    const int wn   = warp >> 1;
    const int wr0  = wm * 64;
    const int wn0  = wn * 32;

    const int lrow0 = tid >> 3;
    const int lk4   = (tid & 7) * 4;

    // ldmatrix lane address bases (byte offsets within a stage)
    const uint32_t aBase = smem_u32 + (uint32_t)(
        ((wr0 + (lane & 7) + ((lane >> 3) & 1) * 8) * GST + (lane >> 4) * 4) * 4);
    const uint32_t bBase = smem_u32 + (uint32_t)(
        (GSTG * G_ASZ +
         (wn0 + (lane >> 4) * 8 + (lane & 7)) * GST + ((lane >> 3) & 1) * 4) * 4);

    float acc[4][4][4];
    #pragma unroll
    for (int mi = 0; mi < 4; mi++)
        #pragma unroll
        for (int ni = 0; ni < 4; ni++)
            #pragma unroll
            for (int r = 0; r < 4; r++) acc[mi][ni][r] = 0.f;

    const int ntiles = K / BK;

    auto prefetch = [&](int k0, int s) {
        #pragma unroll
        for (int it = 0; it < 4; it++) {
            int row = lrow0 + it * 32;
            uint32_t adst = smem_u32 + (uint32_t)((s*G_ASZ + row*GST + lk4) * 4);
            cp_async16(adst, A + (size_t)(bm + row) * lda + k0 + lk4, 16);
            int nrow = bnl + row;
            uint32_t bdst = smem_u32 + (uint32_t)(((GSTG + s)*G_ASZ + row*GST + lk4) * 4);
            cp_async16(bdst, W + (size_t)(nrow < Nloc ? nrow : 0) * K + k0 + lk4,
                       nrow < Nloc ? 16 : 0);
        }
    };

    prefetch(0, 0);      CP_COMMIT();
    prefetch(BK, 1);     CP_COMMIT();

    int st = 0, ps = 2;
    for (int t = 0; t < ntiles; t++) {
        CP_WAIT1();
        __syncthreads();
        if (t + 2 < ntiles) prefetch((t + 2) * BK, ps);
        CP_COMMIT();

        const uint32_t aOff = (uint32_t)(st * G_ASZ * 4);

        #pragma unroll
        for (int kk = 0; kk < BK; kk += 8) {
            uint32_t af[4][4], bf[4][2];
            #pragma unroll
            for (int mi = 0; mi < 4; mi++)
                ldsm_x4(af[mi][0], af[mi][1], af[mi][2], af[mi][3],
                        aBase + aOff + (uint32_t)((mi*16*GST + kk) * 4));
            #pragma unroll
            for (int p = 0; p < 2; p++)
                ldsm_x4(bf[2*p][0], bf[2*p][1], bf[2*p+1][0], bf[2*p+1][1],
                        bBase + aOff + (uint32_t)((p*16*GST + kk) * 4));
            #pragma unroll
            for (int mi = 0; mi < 4; mi++)
                #pragma unroll
                for (int ni = 0; ni < 4; ni++)
                    mma_tf32(acc[mi][ni][0], acc[mi][ni][1],
                             acc[mi][ni][2], acc[mi][ni][3],
                             af[mi][0], af[mi][1], af[mi][2], af[mi][3],
                             bf[ni][0], bf[ni][1]);
        }
        st = (st == 2) ? 0 : st + 1;
        ps = (ps == 2) ? 0 : ps + 1;
    }

    #pragma unroll
    for (int mi = 0; mi < 4; mi++) {
        int row0 = bm + wr0 + mi * 16 + g;
        #pragma unroll
        for (int ni = 0; ni < 4; ni++) {
            int col = bnl + wn0 + ni * 8 + 2 * tg;
            if (col < Nloc) {
                float b0 = bias[col];
                float b1 = bias[col + 1];
                float r0 = acc[mi][ni][0] + b0;
                float r1 = acc[mi][ni][1] + b1;
                float r2 = acc[mi][ni][2] + b0;
                float r3 = acc[mi][ni][3] + b1;
                if (trunc) {
                    r0 = truncf32(r0); r1 = truncf32(r1);
                    r2 = truncf32(r2); r3 = truncf32(r3);
                }
                float* p0 = C + (size_t)row0 * ldc + col;
                float* p1 = C + (size_t)(row0 + 8) * ldc + col;
                p0[0] = r0; p0[1] = r1;
                p1[0] = r2; p1[1] = r3;
            }
        }
    }
}

__global__ void __launch_bounds__(256, 2) gemm_qkvkr(
    const float* __restrict__ xt,
    const float* __restrict__ wt,
    const float* __restrict__ bq,
    const float* __restrict__ bkv,
    const float* __restrict__ bkr,
    float* __restrict__ qb, float* __restrict__ kvb, float* __restrict__ krb)
{
    extern __shared__ float smemf[];
    int bn = blockIdx.x * BN;
    const float *W, *bias; float* C; int ldc, Nloc, bnl; bool trunc;
    if (bn < 2048)      { W = wt + OFF_WQ;  bias = bq;  C = qb;  ldc = 2048; Nloc = 2048; bnl = bn;        trunc = false; }
    else if (bn < 3072) { W = wt + OFF_WKV; bias = bkv; C = kvb; ldc = 1024; Nloc = 1024; bnl = bn - 2048; trunc = true;  }
    else                { W = wt + OFF_WKR; bias = bkr; C = krb; ldc = 64;   Nloc = 64;   bnl = bn - 3072; trunc = false; }
    gemm_core(xt, Dd, W, bias, C, ldc, Nloc, Dd, blockIdx.y * BM, bnl, trunc, smemf);
}

// ---------------------------------------------------------------------------
// RoPE pair helper
// ---------------------------------------------------------------------------
__device__ __forceinline__ void rope_pair_t(float* p, int i, int t, bool trunc)
{
    float inv_freq = powf(10000.f, -(float)i / 32.f);
    float ang = (float)t * inv_freq;
    float s, c;
    sincosf(ang, &s, &c);
    float x1 = p[i];
    float x2 = p[i + 32];
    float y1 = x1 * c - x2 * s;
    float y2 = x2 * c + x1 * s;
    p[i]      = trunc ? truncf32(y1) : y1;
    p[i + 32] = trunc ? truncf32(y2) : y2;
}

#define KUVU_GEMM_BX 24
#define KUVU_ROPE_BX 128

__global__ void __launch_bounds__(256, 2) gemm_kuvu_rope(
    const float* __restrict__ kvb,
    const float* __restrict__ wt,
    const float* __restrict__ bku,
    const float* __restrict__ bvu,
    float* __restrict__ kcb, float* __restrict__ vb,
    float* __restrict__ qb, float* __restrict__ krb)
{
    extern __shared__ float smemf[];
    if (blockIdx.x >= KUVU_GEMM_BX) {
        int row = blockIdx.y * KUVU_ROPE_BX + (blockIdx.x - KUVU_GEMM_BX);
        int t   = row & (Tt - 1);
        for (int item = threadIdx.x; item < 544; item += 256) {
            if (item < 32)
                rope_pair_t(krb + (size_t)row * RDd, item, t, true);
            else {
                int h = (item - 32) >> 5;
                int i = (item - 32) & 31;
                rope_pair_t(qb + (size_t)row * (Hh*HDd) + h*HDd + CDd, i, t, false);
            }
        }
        return;
    }
    int bn = blockIdx.x * BN;
    const float* A; const float *W, *bias; float* C; int ldc, Nloc, bnl;
    if (bn < 1024) { A = kvb;        W = wt + OFF_WKU; bias = bku; C = kcb; ldc = 1024; Nloc = 1024; bnl = bn; }
    else           { A = kvb + LATd; W = wt + OFF_WVU; bias = bvu; C = vb;  ldc = 2048; Nloc = 2048; bnl = bn - 1024; }
    gemm_core(A, 2*LATd, W, bias, C, ldc, Nloc, LATd, blockIdx.y * BM, bnl, true, smemf);
}

__global__ void __launch_bounds__(256, 2) gemm_out(
    const float* __restrict__ ob,
    const float* __restrict__ wt,
    const float* __restrict__ bo,
    float* __restrict__ out)
{
    extern __shared__ float smemf[];
    gemm_core(ob, Hh*HDd, wt + OFF_WO, bo, out, Dd, Dd, Dd,
              blockIdx.y * BM, blockIdx.x * BN, false, smemf);
}

// ---------------------------------------------------------------------------
// Tensor-core flash attention (R14 structure + exp2f): 64-row q blocks,
// 128 threads, single-buffered K/V, 2 CTAs/SM, ldmatrix K/P frags, V via LDS.
// ---------------------------------------------------------------------------
#define A3_SK 132
#define A3_SV 136
#define A3_SP 68
#define A3_SMEM_BYTES ((64*A3_SK + 64*A3_SV + 64*A3_SP) * 4)   // 86016 B

__global__ void __launch_bounds__(128, 2) attn_mma_kernel(
    const float* __restrict__ q,
    const float* __restrict__ kc,
    const float* __restrict__ kr,
    const float* __restrict__ v,
    float* __restrict__ o)
{
    extern __shared__ float smf[];
    float*    Ksf = smf;
    float*    Vsf = smf + 64*A3_SK;
    uint32_t* Ps  = (uint32_t*)(smf + 64*A3_SK + 64*A3_SV);
    const uint32_t smem_u32 = (uint32_t)__cvta_generic_to_shared(smf);

    const int qt   = (Tt/64 - 1) - blockIdx.x;
    const int h    = blockIdx.y;
    const int b    = blockIdx.z;
    const int tid  = threadIdx.x;
    const int warp = tid >> 5;
    const int lane = tid & 31;
    const int g    = lane >> 2;
    const int tg   = lane & 3;
    const int m0   = warp * 16;
    const int qbase = qt * 64;
    const size_t rowbase = (size_t)b * Tt;
    const float scale2 = 0.08838834764831845f * 1.4426950408889634f;  // /sqrt(128)*log2e

    const uint32_t kBase = smem_u32 + (uint32_t)(
        (((lane >> 4) * 8 + (lane & 7)) * A3_SK + ((lane >> 3) & 1) * 4) * 4);
    const uint32_t pBase = smem_u32 + (uint32_t)(
        ((64*A3_SK + 64*A3_SV) +
         (m0 + (lane & 7) + ((lane >> 3) & 1) * 8) * A3_SP + (lane >> 4) * 4) * 4);

    uint32_t aq[16][4];
    {
        const float* qA = q + (rowbase + qbase + m0 + g) * (Hh*HDd) + h*HDd;
        const float* qB = qA + 8 * (Hh*HDd);
        #pragma unroll
        for (int ks = 0; ks < 16; ks++) {
            int k0 = ks * 8;
            aq[ks][0] = f2tf32(qA[k0 + tg]);
            aq[ks][1] = f2tf32(qB[k0 + tg]);
            aq[ks][2] = f2tf32(qA[k0 + tg + 4]);
            aq[ks][3] = f2tf32(qB[k0 + tg + 4]);
        }
    }

    float oacc[16][4];
    #pragma unroll
    for (int na = 0; na < 16; na++)
        #pragma unroll
        for (int r = 0; r < 4; r++) oacc[na][r] = 0.f;

    float mA = -INFINITY, mB = -INFINITY;
    float lA = 0.f, lB = 0.f;

    const int rAg = qbase + m0 + g;
    const int rBg = rAg + 8;

    for (int kb = 0; kb <= qt; kb++) {
        const int kbase = kb * 64;

        #pragma unroll
        for (int it = 0; it < 16; it++) {
            int i  = tid + it * 128;
            int rr = i >> 5;
            int c4 = i & 31;
            size_t trow = rowbase + kbase + rr;
            const float* ksrc = (c4 < 16)
                ? (kc + trow * (Hh*CDd) + h*CDd + c4*4)
                : (kr + trow * RDd + (c4-16)*4);
            uint32_t kdst = smem_u32 + (uint32_t)((rr*A3_SK + c4*4) * 4);
            cp_async16(kdst, ksrc, 16);
            const float* vsrc = v + trow * (Hh*HDd) + h*HDd + c4*4;
            uint32_t vdst = smem_u32 + (uint32_t)((64*A3_SK + rr*A3_SV + c4*4) * 4);
            cp_async16(vdst, vsrc, 16);
        }
        CP_COMMIT();
        CP_WAIT0();
        __syncthreads();

        const uint32_t* Vst = (const uint32_t*)Vsf;

        float sacc[8][4];
        #pragma unroll
        for (int na = 0; na < 8; na++)
            #pragma unroll
            for (int r = 0; r < 4; r++) sacc[na][r] = 0.f;

        #pragma unroll
        for (int ks = 0; ks < 16; ks++) {
            uint32_t kb_[8][2];
            #pragma unroll
            for (int p = 0; p < 4; p++)
                ldsm_x4(kb_[2*p][0], kb_[2*p][1], kb_[2*p+1][0], kb_[2*p+1][1],
                        kBase + (uint32_t)((p*16*A3_SK + ks*8) * 4));
            #pragma unroll
            for (int na = 0; na < 8; na++)
                mma_tf32(sacc[na][0], sacc[na][1], sacc[na][2], sacc[na][3],
                         aq[ks][0], aq[ks][1], aq[ks][2], aq[ks][3],
                         kb_[na][0], kb_[na][1]);
        }

        const bool needmask = (kbase + 63 > rAg);
        float mxA = -INFINITY, mxB = -INFINITY;
        #pragma unroll
        for (int na = 0; na < 8; na++) {
            float s0 = sacc[na][0] * scale2;
            float s1 = sacc[na][1] * scale2;
            float s2 = sacc[na][2] * scale2;
            float s3 = sacc[na][3] * scale2;
            if (needmask) {
                int cg = kbase + na*8 + 2*tg;
                if (cg     > rAg) s0 = -INFINITY;
                if (cg + 1 > rAg) s1 = -INFINITY;
                if (cg     > rBg) s2 = -INFINITY;
                if (cg + 1 > rBg) s3 = -INFINITY;
            }
            sacc[na][0] = s0; sacc[na][1] = s1;
            sacc[na][2] = s2; sacc[na][3] = s3;
            mxA = fmaxf(mxA, fmaxf(s0, s1));
            mxB = fmaxf(mxB, fmaxf(s2, s3));
        }
        mxA = fmaxf(mxA, __shfl_xor_sync(0xffffffff, mxA, 1));
        mxA = fmaxf(mxA, __shfl_xor_sync(0xffffffff, mxA, 2));
        mxB = fmaxf(mxB, __shfl_xor_sync(0xffffffff, mxB, 1));
        mxB = fmaxf(mxB, __shfl_xor_sync(0xffffffff, mxB, 2));

        float mnA = fmaxf(mA, mxA);
        float mnB = fmaxf(mB, mxB);
        float cfA = exp2f(mA - mnA);
        float cfB = exp2f(mB - mnB);
        mA = mnA; mB = mnB;

        float sumA = 0.f, sumB = 0.f;
        uint32_t* prowA = Ps + (m0 + g) * A3_SP;
        uint32_t* prowB = prowA + 8 * A3_SP;
        #pragma unroll
        for (int na = 0; na < 8; na++) {
            int c = na*8 + 2*tg;
            float p0 = exp2f(sacc[na][0] - mA);
            float p1 = exp2f(sacc[na][1] - mA);
            float p2 = exp2f(sacc[na][2] - mB);
            float p3 = exp2f(sacc[na][3] - mB);
            sumA += p0 + p1;
            sumB += p2 + p3;
            prowA[c]     = f2tf32(p0);
            prowA[c + 1] = f2tf32(p1);
            prowB[c]     = f2tf32(p2);
            prowB[c + 1] = f2tf32(p3);
        }
        lA = lA * cfA + sumA;
        lB = lB * cfB + sumB;

        #pragma unroll
        for (int na = 0; na < 16; na++) {
            oacc[na][0] *= cfA; oacc[na][1] *= cfA;
            oacc[na][2] *= cfB; oacc[na][3] *= cfB;
        }

        __syncwarp();

        #pragma unroll
        for (int ks = 0; ks < 8; ks++) {
            uint32_t pa0, pa1, pa2, pa3;
            ldsm_x4(pa0, pa1, pa2, pa3, pBase + (uint32_t)((ks*8) * 4));
            #pragma unroll
            for (int na = 0; na < 16; na++) {
                uint32_t b0 = Vst[(ks*8 + tg)     * A3_SV + na*8 + g];
                uint32_t b1 = Vst[(ks*8 + tg + 4) * A3_SV + na*8 + g];
                mma_tf32(oacc[na][0], oacc[na][1], oacc[na][2], oacc[na][3],
                         pa0, pa1, pa2, pa3, b0, b1);
            }
        }
        __syncthreads();
    }

    lA += __shfl_xor_sync(0xffffffff, lA, 1);
    lA += __shfl_xor_sync(0xffffffff, lA, 2);
    lB += __shfl_xor_sync(0xffffffff, lB, 1);
    lB += __shfl_xor_sync(0xffffffff, lB, 2);
    float invA = 1.f / lA;
    float invB = 1.f / lB;

    float* oA = o + (rowbase + qbase + m0 + g) * (Hh*HDd) + h*HDd;
    float* oB = oA + 8 * (Hh*HDd);
    #pragma unroll
    for (int na = 0; na < 16; na++) {
        int c = na*8 + 2*tg;
        *(float2*)(oA + c) = make_float2(truncf32(oacc[na][0]*invA),
                                         truncf32(oacc[na][1]*invA));
        *(float2*)(oB + c) = make_float2(truncf32(oacc[na][2]*invB),
                                         truncf32(oacc[na][3]*invB));
    }
}

// ---------------------------------------------------------------------------
// Launch: 5 launches; attention is launch 4 (ncu slot).
// ---------------------------------------------------------------------------
extern "C" void kernel_launch(void* const* d_in, const int* in_sizes, int n_in,
                              void* d_out, int out_size)
{
    const float* x   = (const float*)d_in[0];
    const float* Wq  = (const float*)d_in[1];
    const float* bq  = (const float*)d_in[2];
    const float* Wkv = (const float*)d_in[3];
    const float* bkv = (const float*)d_in[4];
    const float* Wkr = (const float*)d_in[5];
    const float* bkr = (const float*)d_in[6];
    const float* Wku = (const float*)d_in[7];
    const float* bku = (const float*)d_in[8];
    const float* Wvu = (const float*)d_in[9];
    const float* bvu = (const float*)d_in[10];
    const float* Wo  = (const float*)d_in[11];
    const float* bo  = (const float*)d_in[12];
    float* out = (float*)d_out;

    float *qb, *kvb, *krb, *kcb, *vb, *ob, *xt, *wt;
    cudaGetSymbolAddress((void**)&qb,  g_q);
    cudaGetSymbolAddress((void**)&kvb, g_kv);
    cudaGetSymbolAddress((void**)&krb, g_kr);
    cudaGetSymbolAddress((void**)&kcb, g_kc);
    cudaGetSymbolAddress((void**)&vb,  g_v);
    cudaGetSymbolAddress((void**)&ob,  g_ao);
    cudaGetSymbolAddress((void**)&xt,  g_xt);
    cudaGetSymbolAddress((void**)&wt,  g_wt);

    cudaFuncSetAttribute(gemm_qkvkr,
                         cudaFuncAttributeMaxDynamicSharedMemorySize, GEMM_SMEM_BYTES);
    cudaFuncSetAttribute(gemm_kuvu_rope,
                         cudaFuncAttributeMaxDynamicSharedMemorySize, GEMM_SMEM_BYTES);
    cudaFuncSetAttribute(gemm_out,
                         cudaFuncAttributeMaxDynamicSharedMemorySize, GEMM_SMEM_BYTES);
    cudaFuncSetAttribute(attn_mma_kernel,
                         cudaFuncAttributeMaxDynamicSharedMemorySize, A3_SMEM_BYTES);

    const dim3 blk(256);

    // 1: convert x + all weights to tf32 bits
    cvt_all<<<CVT_BLOCKS, blk>>>(x, Wq, Wkv, Wkr, Wku, Wvu, Wo, xt, wt);

    // 2: fused q|kv|kr projection (N = 3136 -> 25 col blocks)
    gemm_qkvkr<<<dim3(25, 32), blk, GEMM_SMEM_BYTES>>>(
        xt, wt, bq, bkv, bkr, qb, kvb, krb);

    // 3: fused ku|vu up-projection + rope (extra CTAs)
    gemm_kuvu_rope<<<dim3(KUVU_GEMM_BX + KUVU_ROPE_BX, 32), blk, GEMM_SMEM_BYTES>>>(
        kvb, wt, bku, bvu, kcb, vb, qb, krb);

    // 4: attention (ncu target slot)
    attn_mma_kernel<<<dim3(Tt/64, Hh, Bb), dim3(128), A3_SMEM_BYTES>>>(qb, kcb, krb, vb, ob);

    // 5: output projection
    gemm_out<<<dim3(16, 32), blk, GEMM_SMEM_BYTES>>>(ob, wt, bo, out);
}